// round 11
// baseline (speedup 1.0000x reference)
#include <cuda_runtime.h>

#define BB 8
#define LL 4096
#define DD 1024
#define MAXW 720
#define CH 8               // channels per MA block
#define TILE 1024          // MA output timesteps per block
#define HALO 768           // >= MAXW-1
#define SPAN (TILE + HALO) // 1792 timesteps; 448 quads
#define NQ   (SPAN / 4)    // 448 quad sums per channel
#define PAD 1796           // tile row stride: PAD/4 odd -> bank-clean transposes
#define QP  516            // Q row stride: 512 padded quads + 4 (QP/4 odd)

#define N_DIFF 4096        // diff sub-blocks (16 x 32 x 8)
#define N_MA   2048        // MA  sub-blocks (64 x 4 x 8)

#define SM_Q   (CH * PAD)              // Q array offset (floats)
#define SM_ALL (SM_Q + CH * QP)        // total floats (~72.3 KB)

__global__ __launch_bounds__(256, 3) void fused_kernel(const float* __restrict__ u,
                                                       const float* __restrict__ dk,
                                                       const float* __restrict__ ma_k,
                                                       float* __restrict__ out) {
    const int m = blockIdx.x % 3;
    const int q = blockIdx.x / 3;
    const int tid  = threadIdx.x;
    const int warp = tid >> 5;
    const int lane = tid & 31;

    if (m != 2) {
        // =============== diff body: 4-tap causal stencil =================
        const int id = q * 2 + m;              // 0..4095
        const int g  = id & 15;
        const int gy = (id >> 4) & 31;
        const int b  = id >> 9;

        const int d  = g * 64 + lane;          // even 32-channel group
        const int t0 = (gy * 8 + warp) * 16;

        const int nk = (d >> 3) & 3;
        const float c0 = dk[nk * 4 + 0];
        const float c1 = dk[nk * 4 + 1];
        const float c2 = dk[nk * 4 + 2];
        const float c3 = dk[nk * 4 + 3];

        const size_t base = (size_t)b * LL * DD + d;

        float x1 = (t0 >= 1) ? u[base + (size_t)(t0 - 1) * DD] : 0.0f;
        float x2 = (t0 >= 2) ? u[base + (size_t)(t0 - 2) * DD] : 0.0f;
        float x3 = (t0 >= 3) ? u[base + (size_t)(t0 - 3) * DD] : 0.0f;

        #pragma unroll
        for (int tt = 0; tt < 16; tt++) {
            const int t = t0 + tt;
            const float x0 = u[base + (size_t)t * DD];
            __stcs(&out[base + (size_t)t * DD],
                   c0 * x0 + c1 * x1 + c2 * x2 + c3 * x3);
            x3 = x2; x2 = x1; x1 = x0;
        }
        return;
    }

    // =============== MA body: quad-sum prefix decomposition ==============
    extern __shared__ float sm[];
    float* tile = sm;                // CH * PAD  : raw x, channel-major
    float* Qa   = sm + SM_Q;         // CH * QP   : quad sums -> exclusive SQ

    const int grp = q & 63;                    // 8-channel group
    const int lt  = (q >> 6) & 3;              // L-tile 0..3
    const int b   = q >> 8;                    // batch
    const int g32 = 2 * (grp >> 2) + 1;        // odd 32-channel group
    const int d0  = g32 * 32 + (grp & 3) * 8;
    const int T0  = lt * TILE;

    const float4* u4 = (const float4*)u;
    float4*       o4 = (float4*)out;
    const size_t base4 = (size_t)b * LL * (DD / 4) + (d0 >> 2);

    const int c4 = tid & 1;          // float4 column (8 ch = 2 float4)
    const int gq = tid >> 1;         // quad-row group 0..127

    // per-thread params for its 4 phase-C channels
    float m1r[4]; int wr[4], dlr[4];
    #pragma unroll
    for (int j = 0; j < 4; j++) {
        const int d = d0 + c4 * 4 + j;
        const int i_ma = ((d >> 6) << 2) + ((d >> 3) & 7) - 4;   // 0..63
        m1r[j] = __ldg(&ma_k[i_ma * MAXW + 1]);                  // = -1/w
        wr[j]  = (int)rintf(-1.0f / m1r[j]);
        dlr[j] = (-wr[j]) & 3;
    }

    // ---- Phase A: load+transpose x, emit quad sums, zero Q padding ----
    {
        #pragma unroll
        for (int k = 0; k < 3; k++) {
            const int r4 = gq * 4 + k * 512;
            float4 f[4];
            #pragma unroll
            for (int j = 0; j < 4; j++) {
                const int t = T0 - HALO + r4 + j;
                f[j] = (t >= 0) ? u4[base4 + (size_t)t * (DD / 4) + c4]
                                : make_float4(0.f, 0.f, 0.f, 0.f);
            }
            #pragma unroll
            for (int j = 0; j < 4; j++) {
                float4 qv = make_float4(((const float*)&f[0])[j], ((const float*)&f[1])[j],
                                        ((const float*)&f[2])[j], ((const float*)&f[3])[j]);
                *(float4*)(tile + (c4 * 4 + j) * PAD + r4) = qv;
                Qa[(c4 * 4 + j) * QP + (r4 >> 2)] = qv.x + qv.y + qv.z + qv.w;
            }
        }
        if (tid < 128) {
            const int c4t = tid & 1;
            const int r4  = 1536 + (tid >> 1) * 4;
            float4 f[4];
            #pragma unroll
            for (int j = 0; j < 4; j++) {
                const int t = T0 - HALO + r4 + j;
                f[j] = (t >= 0) ? u4[base4 + (size_t)t * (DD / 4) + c4t]
                                : make_float4(0.f, 0.f, 0.f, 0.f);
            }
            #pragma unroll
            for (int j = 0; j < 4; j++) {
                float4 qv = make_float4(((const float*)&f[0])[j], ((const float*)&f[1])[j],
                                        ((const float*)&f[2])[j], ((const float*)&f[3])[j]);
                *(float4*)(tile + (c4t * 4 + j) * PAD + r4) = qv;
                Qa[(c4t * 4 + j) * QP + (r4 >> 2)] = qv.x + qv.y + qv.z + qv.w;
            }
        } else {
            // zero Q padding quads 448..511 (128 tasks: 8 ch x 16 float4)
            const int tt = tid - 128;
            const int ch = tt >> 4;
            const int qi = 448 + (tt & 15) * 4;
            *(float4*)(Qa + ch * QP + qi) = make_float4(0.f, 0.f, 0.f, 0.f);
        }
    }
    __syncthreads();

    // ---- Phase B: warp w scans channel w's 512 quad sums -> exclusive SQ,
    //      in place, conflict-free (quad at lane*4), 4 short sub-scans ----
    {
        float* qrow = Qa + warp * QP;
        float carry = 0.0f;
        #pragma unroll
        for (int sb = 0; sb < 4; sb++) {
            float4 qv = *(const float4*)(qrow + sb * 128 + lane * 4);
            float4 p;
            p.x = qv.x; p.y = p.x + qv.y; p.z = p.y + qv.z; p.w = p.z + qv.w;
            float v = p.w;
            #pragma unroll
            for (int off = 1; off < 32; off <<= 1) {
                const float n = __shfl_up_sync(0xffffffffu, v, off);
                if (lane >= off) v += n;
            }
            const float base = (v - p.w) + carry;     // exclusive of this lane
            float4 E;                                  // SQ_exc at qi..qi+3
            E.x = base; E.y = base + p.x; E.z = base + p.y; E.w = base + p.z;
            *(float4*)(qrow + sb * 128 + lane * 4) = E;
            carry += __shfl_sync(0xffffffffu, v, 31);
        }
    }
    __syncthreads();

    // ---- Phase C: y = x + m1*(S[t] - S[t-w]) from x quads + SQ scalars ----
    #pragma unroll
    for (int it = 0; it < 2; it++) {
        const int r4 = gq * 4 + it * 512;            // output rows 0..1023
        const int hr = HALO + r4;
        float4 yt[4];
        #pragma unroll
        for (int j = 0; j < 4; j++) {
            const int ch = c4 * 4 + j;
            const float* trow = tile + ch * PAD;
            const float* qrow = Qa + ch * QP;

            const float4 x = *(const float4*)(trow + hr);
            const float SQt = qrow[hr >> 2];
            const float i0 = x.x, i1 = i0 + x.y, i2 = i1 + x.z, i3 = i2 + x.w;

            const int tw = hr - wr[j];
            const int al = tw & ~3;
            const float4 lo = *(const float4*)(trow + al);
            const float4 hi = *(const float4*)(trow + al + 4);
            const float SQlo = qrow[al >> 2];
            const float SQhi = qrow[(al >> 2) + 1];
            const float L0 = SQlo + lo.x, L1 = L0 + lo.y, L2 = L1 + lo.z, L3 = L2 + lo.w;
            const float H0 = SQhi + hi.x, H1 = H0 + hi.y, H2 = H1 + hi.z;

            float4 so;
            const int dlt = dlr[j];
            if      (dlt == 0) so = make_float4(L0, L1, L2, L3);
            else if (dlt == 1) so = make_float4(L1, L2, L3, H0);
            else if (dlt == 2) so = make_float4(L2, L3, H0, H1);
            else               so = make_float4(L3, H0, H1, H2);

            const float m1 = m1r[j];
            float4 y;
            y.x = fmaf(m1, SQt + i0 - so.x, x.x);
            y.y = fmaf(m1, SQt + i1 - so.y, x.y);
            y.z = fmaf(m1, SQt + i2 - so.z, x.z);
            y.w = fmaf(m1, SQt + i3 - so.w, x.w);
            yt[j] = y;
        }
        #pragma unroll
        for (int j = 0; j < 4; j++) {
            float4 o = make_float4(((const float*)&yt[0])[j], ((const float*)&yt[1])[j],
                                   ((const float*)&yt[2])[j], ((const float*)&yt[3])[j]);
            __stcs(&o4[base4 + (size_t)(T0 + r4 + j) * (DD / 4) + c4], o);
        }
    }
}

extern "C" void kernel_launch(void* const* d_in, const int* in_sizes, int n_in,
                              void* d_out, int out_size) {
    const float* u  = (const float*)d_in[0];   // (B, L, D)
    const float* dk = (const float*)d_in[1];   // (64, 4)
    const float* mk = (const float*)d_in[2];   // (64, 720)
    float* out = (float*)d_out;                // (B, L, D)

    const size_t smem = (size_t)SM_ALL * sizeof(float);   // ~72.3 KB
    cudaFuncSetAttribute(fused_kernel, cudaFuncAttributeMaxDynamicSharedMemorySize, (int)smem);

    fused_kernel<<<N_DIFF + N_MA, 256, smem>>>(u, dk, mk, out);
}

// round 12
// speedup vs baseline: 1.1577x; 1.1577x over previous
#include <cuda_runtime.h>

#define BB 8
#define LL 4096
#define DD 1024
#define MAXW 720
#define CH 8               // channels per MA block
#define TILE 1024          // MA output timesteps per block
#define HALO 768           // >= MAXW-1
#define SPAN (TILE + HALO) // 1792 = 7 * 256
#define NSB  (SPAN / 256)  // 7 sub-blocks
#define PAD 1796           // row stride: PAD/4 odd -> bank-clean transposes

#define N_DIFF 4096        // diff sub-blocks (16 x 32 x 8)
#define N_MA   2048        // MA  sub-blocks (64 x 4 x 8)

#define SM_TOT (CH * PAD)
#define SM_OFF (SM_TOT + CH * 8)
#define SM_ALL (SM_OFF + CH * 8)

__global__ __launch_bounds__(256, 4) void fused_kernel(const float* __restrict__ u,
                                                       const float* __restrict__ dk,
                                                       const float* __restrict__ ma_k,
                                                       float* __restrict__ out) {
    const int m = blockIdx.x % 3;
    const int q = blockIdx.x / 3;
    const int tid  = threadIdx.x;
    const int warp = tid >> 5;
    const int lane = tid & 31;

    if (m != 2) {
        // =============== diff body: 4-tap causal stencil =================
        const int id = q * 2 + m;              // 0..4095
        const int g  = id & 15;
        const int gy = (id >> 4) & 31;
        const int b  = id >> 9;

        const int d  = g * 64 + lane;          // even 32-channel group
        const int t0 = (gy * 8 + warp) * 16;

        const int nk = (d >> 3) & 3;
        const float c0 = dk[nk * 4 + 0];
        const float c1 = dk[nk * 4 + 1];
        const float c2 = dk[nk * 4 + 2];
        const float c3 = dk[nk * 4 + 3];

        const size_t base = (size_t)b * LL * DD + d;

        float x1 = (t0 >= 1) ? u[base + (size_t)(t0 - 1) * DD] : 0.0f;
        float x2 = (t0 >= 2) ? u[base + (size_t)(t0 - 2) * DD] : 0.0f;
        float x3 = (t0 >= 3) ? u[base + (size_t)(t0 - 3) * DD] : 0.0f;

        #pragma unroll
        for (int tt = 0; tt < 16; tt++) {
            const int t = t0 + tt;
            const float x0 = u[base + (size_t)t * DD];
            __stcs(&out[base + (size_t)t * DD],
                   c0 * x0 + c1 * x1 + c2 * x2 + c3 * x3);
            x3 = x2; x2 = x1; x1 = x0;
        }
        return;
    }

    // =============== MA body: decoupled local prefix-sum tiles ===========
    extern __shared__ float sm[];
    float* tile   = sm;              // CH * PAD
    float* totals = sm + SM_TOT;     // CH * 8
    float* offs   = sm + SM_OFF;     // CH * 8

    const int grp = q & 63;                    // 8-channel group
    const int lt  = (q >> 6) & 3;              // L-tile 0..3
    const int b   = q >> 8;                    // batch
    const int g32 = 2 * (grp >> 2) + 1;        // odd 32-channel group
    const int d0  = g32 * 32 + (grp & 3) * 8;
    const int T0  = lt * TILE;

    const float4* u4 = (const float4*)u;
    float4*       o4 = (float4*)out;
    const size_t base4 = (size_t)b * LL * (DD / 4) + (d0 >> 2);

    const int c4 = tid & 1;          // float4 column (8 ch = 2 float4)
    const int gq = tid >> 1;         // quad-row group 0..127

    // ---- Phase A: load 4 rows/thread, register transpose, STS.128 ----
    {
        #pragma unroll
        for (int k = 0; k < 3; k++) {
            const int r4 = gq * 4 + k * 512;
            float4 f[4];
            #pragma unroll
            for (int j = 0; j < 4; j++) {
                const int t = T0 - HALO + r4 + j;
                f[j] = (t >= 0) ? u4[base4 + (size_t)t * (DD / 4) + c4]
                                : make_float4(0.f, 0.f, 0.f, 0.f);
            }
            #pragma unroll
            for (int j = 0; j < 4; j++) {
                float4 qv = make_float4(((const float*)&f[0])[j], ((const float*)&f[1])[j],
                                        ((const float*)&f[2])[j], ((const float*)&f[3])[j]);
                *(float4*)(tile + (c4 * 4 + j) * PAD + r4) = qv;
            }
        }
        if (tid < 128) {
            const int c4t = tid & 1;
            const int r4  = 1536 + (tid >> 1) * 4;
            float4 f[4];
            #pragma unroll
            for (int j = 0; j < 4; j++) {
                const int t = T0 - HALO + r4 + j;
                f[j] = (t >= 0) ? u4[base4 + (size_t)t * (DD / 4) + c4t]
                                : make_float4(0.f, 0.f, 0.f, 0.f);
            }
            #pragma unroll
            for (int j = 0; j < 4; j++) {
                float4 qv = make_float4(((const float*)&f[0])[j], ((const float*)&f[1])[j],
                                        ((const float*)&f[2])[j], ((const float*)&f[3])[j]);
                *(float4*)(tile + (c4t * 4 + j) * PAD + r4) = qv;
            }
        }
    }
    __syncthreads();

    // ---- Phase B1: warp w -> channel w, 7 independent 256-scans,
    //      conflict-free layout: lane owns quads at lane*4 and lane*4+128 ----
    {
        float* trow = tile + warp * PAD;
        #pragma unroll
        for (int s = 0; s < NSB; s++) {
            float4 a  = *(const float4*)(trow + s * 256 + lane * 4);
            float4 bq = *(const float4*)(trow + s * 256 + 128 + lane * 4);
            float4 pa, pb;
            pa.x = a.x;  pa.y = pa.x + a.y;  pa.z = pa.y + a.z;  pa.w = pa.z + a.w;
            pb.x = bq.x; pb.y = pb.x + bq.y; pb.z = pb.y + bq.z; pb.w = pb.z + bq.w;
            float vA = pa.w, vB = pb.w;
            #pragma unroll
            for (int off = 1; off < 32; off <<= 1) {
                const float nA = __shfl_up_sync(0xffffffffu, vA, off);
                const float nB = __shfl_up_sync(0xffffffffu, vB, off);
                if (lane >= off) { vA += nA; vB += nB; }
            }
            const float T128 = __shfl_sync(0xffffffffu, vA, 31);
            const float eA = vA - pa.w;
            const float eB = vB - pb.w + T128;
            pa.x += eA; pa.y += eA; pa.z += eA; pa.w += eA;
            pb.x += eB; pb.y += eB; pb.z += eB; pb.w += eB;
            *(float4*)(trow + s * 256 + lane * 4)       = pa;
            *(float4*)(trow + s * 256 + 128 + lane * 4) = pb;
            if (lane == 31) totals[warp * 8 + s] = pb.w;   // 256-total
        }
    }
    __syncthreads();

    // ---- Phase B2: per-channel exclusive prefix of sub-block totals ----
    if (tid < CH * NSB) {
        const int ch = tid / NSB;
        const int s  = tid - ch * NSB;
        float off = 0.0f;
        #pragma unroll
        for (int k = 0; k < NSB - 1; k++)
            if (k < s) off += totals[ch * 8 + k];
        offs[ch * 8 + s] = off;
    }
    __syncthreads();

    // per-thread params for its 4 phase-C channels (live range: phase C only)
    float m1r[4]; int wr[4], dlr[4];
    #pragma unroll
    for (int j = 0; j < 4; j++) {
        const int d = d0 + c4 * 4 + j;
        const int i_ma = ((d >> 6) << 2) + ((d >> 3) & 7) - 4;   // 0..63
        m1r[j] = __ldg(&ma_k[i_ma * MAXW + 1]);                  // = -1/w
        wr[j]  = (int)rintf(-1.0f / m1r[j]);
        dlr[j] = (-wr[j]) & 3;
    }

    // ---- Phase C: compute y in registers, transpose, streaming STG.128 ----
    #pragma unroll
    for (int it = 0; it < 2; it++) {
        const int r4 = gq * 4 + it * 512;            // output rows 0..1023
        const int hr = HALO + r4;
        float4 yt[4];
        #pragma unroll
        for (int j = 0; j < 4; j++) {
            const int ch = c4 * 4 + j;
            const float* trow = tile + ch * PAD;
            const float oS = offs[ch * 8 + (hr >> 8)];
            const float4 S = *(const float4*)(trow + hr);

            // S[hr-1]: lane-2 holds quad hr-4 of the same channel
            float smw = __shfl_up_sync(0xffffffffu, S.w, 2);
            if ((lane >> 1) == 0) smw = trow[hr - 1];
            const float Sm = smw + offs[ch * 8 + ((hr - 1) >> 8)];

            const int tw = hr - wr[j];
            const int al = tw & ~3;
            const float4 lo = *(const float4*)(trow + al);
            const float4 hi = *(const float4*)(trow + al + 4);
            const float olo = offs[ch * 8 + (al >> 8)];
            const float ohi = offs[ch * 8 + ((al + 4) >> 8)];
            float4 so, oo;
            const int dlt = dlr[j];
            if      (dlt == 0) { so = lo;
                                 oo = make_float4(olo, olo, olo, olo); }
            else if (dlt == 1) { so = make_float4(lo.y, lo.z, lo.w, hi.x);
                                 oo = make_float4(olo, olo, olo, ohi); }
            else if (dlt == 2) { so = make_float4(lo.z, lo.w, hi.x, hi.y);
                                 oo = make_float4(olo, olo, ohi, ohi); }
            else               { so = make_float4(lo.w, hi.x, hi.y, hi.z);
                                 oo = make_float4(olo, ohi, ohi, ohi); }

            const float m1 = m1r[j];
            float4 y;
            y.x = (S.x + oS - Sm)  + m1 * (S.x + oS - so.x - oo.x);
            y.y = (S.y - S.x)      + m1 * (S.y + oS - so.y - oo.y);
            y.z = (S.z - S.y)      + m1 * (S.z + oS - so.z - oo.z);
            y.w = (S.w - S.z)      + m1 * (S.w + oS - so.w - oo.w);
            yt[j] = y;
        }
        #pragma unroll
        for (int j = 0; j < 4; j++) {
            float4 o = make_float4(((const float*)&yt[0])[j], ((const float*)&yt[1])[j],
                                   ((const float*)&yt[2])[j], ((const float*)&yt[3])[j]);
            __stcs(&o4[base4 + (size_t)(T0 + r4 + j) * (DD / 4) + c4], o);
        }
    }
}

extern "C" void kernel_launch(void* const* d_in, const int* in_sizes, int n_in,
                              void* d_out, int out_size) {
    const float* u  = (const float*)d_in[0];   // (B, L, D)
    const float* dk = (const float*)d_in[1];   // (64, 4)
    const float* mk = (const float*)d_in[2];   // (64, 720)
    float* out = (float*)d_out;                // (B, L, D)

    const size_t smem = (size_t)SM_ALL * sizeof(float);   // 57,984 B (x4 fits 228KB)
    cudaFuncSetAttribute(fused_kernel, cudaFuncAttributeMaxDynamicSharedMemorySize, (int)smem);

    fused_kernel<<<N_DIFF + N_MA, 256, smem>>>(u, dk, mk, out);
}